// round 11
// baseline (speedup 1.0000x reference)
#include <cuda_runtime.h>
#include <cuda_fp16.h>
#include <math.h>

#define FULLM 0xffffffffu
static const int NMAX = 100352;
static const int EMAX = 1700000;
static const int NB  = 888;     // 148 SMs x 6 resident blocks
static const int TPB = 256;

// ---------------- device scratch ----------------
__device__ long long d_musum[256];
__device__ unsigned d_bar = 0;
__device__ unsigned d_gen = 0;
__device__ __align__(16) int d_cnt[NMAX];
__device__ int      d_cur[NMAX];
__device__ int      d_off[NMAX + 1];
__device__ float    d_dinv[NMAX];
__device__ int      d_col[EMAX];
__device__ float    d_se[EMAX];        // dinv[src] per CSR slot
__device__ uint2    d_ga[NMAX * 32];   // layer-0 cnt (fp16 exact)
__device__ uint2    d_gb[NMAX * 32];   // layer-1 cnt
__device__ uint2    d_g2[NMAX * 10];   // layer-2 cnt (40 feats)
__device__ __align__(16) unsigned d_wb0[8 * 128];
__device__ __align__(16) unsigned d_wb1[4 * 128];
__device__ __align__(16) unsigned d_wb2[4 * 40];
__device__ __align__(16) float d_al0[128];
__device__ __align__(16) float d_al1[128];
__device__ __align__(16) float d_al2[40];

__device__ __forceinline__ void gsync() {
    __threadfence();                  // publish this thread's writes
    __syncthreads();
    if (threadIdx.x == 0) {
        unsigned g = *((volatile unsigned*)&d_gen);
        unsigned t = atomicAdd(&d_bar, 1);
        if (t == NB - 1) {
            atomicExch(&d_bar, 0);
            __threadfence();
            atomicAdd(&d_gen, 1);
        } else {
            while (*((volatile unsigned*)&d_gen) == g) __nanosleep(128);
        }
        __threadfence();
    }
    __syncthreads();
}

__device__ __forceinline__ int detect64(const void* e) {
    const unsigned* w = (const unsigned*)e;
    int lane = threadIdx.x & 31;
    unsigned h0 = w[2 * lane + 1];
    unsigned h1 = w[64 + 2 * lane + 1];
    int z = __popc(__ballot_sync(FULLM, h0 == 0)) + __popc(__ballot_sync(FULLM, h1 == 0));
    return z >= 32;
}
__device__ __forceinline__ int ld_edge(const void* e, long long idx, int is64) {
    return is64 ? (int)((const long long*)e)[idx] : ((const int*)e)[idx];
}

__device__ __forceinline__ void accH(float4& a, uint2 u, float s) {
    float2 f0 = __half22float2(*reinterpret_cast<__half2*>(&u.x));
    float2 f1 = __half22float2(*reinterpret_cast<__half2*>(&u.y));
    a.x += s * f0.x; a.y += s * f0.y; a.z += s * f1.x; a.w += s * f1.y;
}

__device__ __forceinline__ float4 gather128(const uint2* __restrict__ gp, int wid, int lane) {
    float4 A = make_float4(0.f, 0.f, 0.f, 0.f), B = A;
    accH(A, gp[wid * 32 + lane], d_dinv[wid]);   // self loop
    int k = d_off[wid], k1 = d_off[wid + 1];
    for (; k + 8 <= k1; k += 8) {
        int c[8]; float s[8]; uint2 u[8];
#pragma unroll
        for (int j = 0; j < 8; j++) c[j] = d_col[k + j];
#pragma unroll
        for (int j = 0; j < 8; j++) s[j] = d_se[k + j];
#pragma unroll
        for (int j = 0; j < 8; j++) u[j] = gp[c[j] * 32 + lane];
#pragma unroll
        for (int j = 0; j < 8; j++) accH((j & 1) ? B : A, u[j], s[j]);
    }
    if (k + 4 <= k1) {
        int c[4]; float s[4]; uint2 u[4];
#pragma unroll
        for (int j = 0; j < 4; j++) c[j] = d_col[k + j];
#pragma unroll
        for (int j = 0; j < 4; j++) s[j] = d_se[k + j];
#pragma unroll
        for (int j = 0; j < 4; j++) u[j] = gp[c[j] * 32 + lane];
#pragma unroll
        for (int j = 0; j < 4; j++) accH((j & 1) ? B : A, u[j], s[j]);
        k += 4;
    }
    for (; k < k1; k++) {
        int c = d_col[k];
        accH(B, gp[c * 32 + lane], d_se[k]);
    }
    A.x += B.x; A.y += B.y; A.z += B.z; A.w += B.w;
    return A;
}

__device__ __forceinline__ void sign_words(float v0, float v1, float v2, float v3,
                                           int lane, unsigned bw[4]) {
    unsigned nib = (unsigned)(v0 > 0.f) | ((unsigned)(v1 > 0.f) << 1) |
                   ((unsigned)(v2 > 0.f) << 2) | ((unsigned)(v3 > 0.f) << 3);
    unsigned sh = nib << ((lane & 7) * 4);
    sh |= __shfl_xor_sync(FULLM, sh, 1);
    sh |= __shfl_xor_sync(FULLM, sh, 2);
    sh |= __shfl_xor_sync(FULLM, sh, 4);
#pragma unroll
    for (int wd = 0; wd < 4; wd++) bw[wd] = __shfl_sync(FULLM, sh, wd * 8);
}

// ================= THE persistent mega-kernel =================
__global__ void __launch_bounds__(TPB, 6)
k_mega(const float* __restrict__ x,
       const void* __restrict__ e, long long E, int n,
       const float* __restrict__ W0, const float* __restrict__ b0,
       const float* __restrict__ W1, const float* __restrict__ b1,
       const float* __restrict__ W2, const float* __restrict__ b2,
       float* __restrict__ out) {
    int bid = blockIdx.x;
    int tid = threadIdx.x;
    int warp = tid >> 5, lane = tid & 31;
    int wb64 = (n + 63) / 64;

    // ---------- P1: colsum (blocks 0-639) | wprep (640-676) | deg (677-887) ----------
    if (bid < 640) {
        int rows = (n + 639) / 640;
        int r0 = bid * rows, r1 = min(n, r0 + rows);
        float s0 = 0.f, s1 = 0.f, s2 = 0.f, s3 = 0.f;
        int r = r0;
        for (; r + 4 <= r1; r += 4) {
            s0 += x[(long long)r * 256 + tid];
            s1 += x[(long long)(r + 1) * 256 + tid];
            s2 += x[(long long)(r + 2) * 256 + tid];
            s3 += x[(long long)(r + 3) * 256 + tid];
        }
        for (; r < r1; r++) s0 += x[(long long)r * 256 + tid];
        float s = (s0 + s1) + (s2 + s3);
        long long q = llrintf(s * 4194304.f);
        atomicAdd((unsigned long long*)&d_musum[tid], (unsigned long long)q);
    } else if (bid < 677) {
        int W = (bid - 640) * 8 + warp;
        const float* Wsrc; unsigned* wbT; float* alpha; int K, OUT, j;
        bool act = true;
        if (W < 128)      { Wsrc = W0; wbT = d_wb0; alpha = d_al0; K = 256; OUT = 128; j = W; }
        else if (W < 256) { Wsrc = W1; wbT = d_wb1; alpha = d_al1; K = 128; OUT = 128; j = W - 128; }
        else if (W < 296) { Wsrc = W2; wbT = d_wb2; alpha = d_al2; K = 128; OUT = 40;  j = W - 256; }
        else act = false;
        if (act) {
            float s = 0.f;
            int KW = K / 32;
            for (int w = 0; w < KW; w++) {
                float v = Wsrc[(long long)(w * 32 + lane) * OUT + j];
                s += fabsf(v);
                unsigned m = __ballot_sync(FULLM, v > 0.f);
                if (lane == 0) wbT[w * OUT + j] = m;
            }
            for (int o = 16; o; o >>= 1) s += __shfl_xor_sync(FULLM, s, o);
            if (lane == 0) alpha[j] = s / (float)K;
        }
    } else {
        int is64 = detect64(e);
        for (long long i = (long long)(bid - 677) * TPB + tid; i < E; i += 211LL * TPB)
            atomicAdd(&d_cnt[ld_edge(e, E + i, is64)], 1);
    }
    gsync();

    // ---------- P2: scan (block 0) | bnpack+bmm0 (blocks 1-887) ----------
    if (bid == 0) {
        __shared__ int wsum[8];
        int chunk = ((n + 255) / 256 + 3) & ~3;
        int c0 = tid * chunk, c1 = min(n, c0 + chunk);
        int s = 0, i = c0;
        for (; i + 4 <= c1; i += 4) {
            int4 v = *(const int4*)(d_cnt + i);
            s += v.x + v.y + v.z + v.w;
        }
        for (; i < c1; i++) s += d_cnt[i];
        int incl = s;
        for (int o = 1; o < 32; o <<= 1) {
            int v = __shfl_up_sync(FULLM, incl, o);
            if (lane >= o) incl += v;
        }
        if (lane == 31) wsum[warp] = incl;
        __syncthreads();
        if (warp == 0) {
            int v = (lane < 8) ? wsum[lane] : 0;
            for (int o = 1; o < 8; o <<= 1) {
                int u = __shfl_up_sync(FULLM, v, o);
                if (lane >= o) v += u;
            }
            if (lane < 8) wsum[lane] = v;
        }
        __syncthreads();
        int run = incl - s + (warp ? wsum[warp - 1] : 0);
        for (i = c0; i < c1; i++) {
            int c = d_cnt[i];
            d_off[i] = run;
            run += c;
            d_dinv[i] = rsqrtf((float)(c + 1));
        }
        if (c0 < n && c1 == n) d_off[n] = run;
    } else {
        __shared__ float smu[256];
        smu[tid] = (float)((double)d_musum[tid] / (4194304.0 * (double)n));
        __syncthreads();
        uint4 wv[8];
#pragma unroll
        for (int w = 0; w < 8; w++) wv[w] = *(const uint4*)&d_wb0[w * 128 + 4 * lane];
        for (int c = bid - 1; c < wb64; c += NB - 1) {
            int n0 = c * 64 + warp * 8;
#pragma unroll
            for (int i = 0; i < 8; i++) {
                int node = n0 + i;
                if (node >= n) break;
                const float* xr = x + (long long)node * 256;
                unsigned bw[8];
#pragma unroll
                for (int w = 0; w < 8; w++) {
                    float v = xr[w * 32 + lane];
                    bw[w] = __ballot_sync(FULLM, v > smu[w * 32 + lane]);
                }
                int p0 = 0, p1 = 0, p2 = 0, p3 = 0;
#pragma unroll
                for (int w = 0; w < 8; w++) {
                    p0 += __popc(bw[w] ^ wv[w].x);
                    p1 += __popc(bw[w] ^ wv[w].y);
                    p2 += __popc(bw[w] ^ wv[w].z);
                    p3 += __popc(bw[w] ^ wv[w].w);
                }
                __half2 h0 = __floats2half2_rn((float)(256 - 2 * p0), (float)(256 - 2 * p1));
                __half2 h1 = __floats2half2_rn((float)(256 - 2 * p2), (float)(256 - 2 * p3));
                uint2 u;
                u.x = *(unsigned*)&h0;
                u.y = *(unsigned*)&h1;
                d_ga[node * 32 + lane] = u;
            }
        }
    }
    gsync();

    // ---------- P3: CSR fill ----------
    {
        int is64 = detect64(e);
        for (long long i = (long long)bid * TPB + tid; i < E; i += (long long)NB * TPB) {
            int sv = ld_edge(e, i, is64);
            int dv = ld_edge(e, E + i, is64);
            int pos = d_off[dv] + atomicAdd(&d_cur[dv], 1);
            d_col[pos] = sv;
            d_se[pos] = d_dinv[sv];
        }
    }
    gsync();

    // ---------- P4: agg(layer-0) + sign + bmm1 -> d_gb ----------
    {
        uint4 wv[4];
#pragma unroll
        for (int w = 0; w < 4; w++) wv[w] = *(const uint4*)&d_wb1[w * 128 + 4 * lane];
        float4 al = ((const float4*)d_al0)[lane];
        float4 b  = ((const float4*)b0)[lane];
        for (int wid = bid * 8 + warp; wid < n; wid += NB * 8) {
            float4 A = gather128(d_ga, wid, lane);
            float di = d_dinv[wid];
            float v0 = A.x * al.x * di + b.x;
            float v1 = A.y * al.y * di + b.y;
            float v2 = A.z * al.z * di + b.z;
            float v3 = A.w * al.w * di + b.w;
            unsigned bw[4];
            sign_words(v0, v1, v2, v3, lane, bw);
            int p0 = 0, p1 = 0, p2 = 0, p3 = 0;
#pragma unroll
            for (int w = 0; w < 4; w++) {
                p0 += __popc(bw[w] ^ wv[w].x);
                p1 += __popc(bw[w] ^ wv[w].y);
                p2 += __popc(bw[w] ^ wv[w].z);
                p3 += __popc(bw[w] ^ wv[w].w);
            }
            __half2 h0 = __floats2half2_rn((float)(128 - 2 * p0), (float)(128 - 2 * p1));
            __half2 h1 = __floats2half2_rn((float)(128 - 2 * p2), (float)(128 - 2 * p3));
            uint2 u;
            u.x = *(unsigned*)&h0;
            u.y = *(unsigned*)&h1;
            d_gb[wid * 32 + lane] = u;
        }
    }
    gsync();

    // ---------- P5: agg(layer-1) + sign + bmm2 -> d_g2 ----------
    {
        uint4 wv[4];
        if (lane < 10) {
#pragma unroll
            for (int w = 0; w < 4; w++) wv[w] = *(const uint4*)&d_wb2[w * 40 + 4 * lane];
        }
        float4 al = ((const float4*)d_al1)[lane];
        float4 b  = ((const float4*)b1)[lane];
        for (int wid = bid * 8 + warp; wid < n; wid += NB * 8) {
            float4 A = gather128(d_gb, wid, lane);
            float di = d_dinv[wid];
            float v0 = A.x * al.x * di + b.x;
            float v1 = A.y * al.y * di + b.y;
            float v2 = A.z * al.z * di + b.z;
            float v3 = A.w * al.w * di + b.w;
            unsigned bw[4];
            sign_words(v0, v1, v2, v3, lane, bw);
            if (lane < 10) {
                int p0 = 0, p1 = 0, p2 = 0, p3 = 0;
#pragma unroll
                for (int w = 0; w < 4; w++) {
                    p0 += __popc(bw[w] ^ wv[w].x);
                    p1 += __popc(bw[w] ^ wv[w].y);
                    p2 += __popc(bw[w] ^ wv[w].z);
                    p3 += __popc(bw[w] ^ wv[w].w);
                }
                __half2 h0 = __floats2half2_rn((float)(128 - 2 * p0), (float)(128 - 2 * p1));
                __half2 h1 = __floats2half2_rn((float)(128 - 2 * p2), (float)(128 - 2 * p3));
                uint2 u;
                u.x = *(unsigned*)&h0;
                u.y = *(unsigned*)&h1;
                d_g2[wid * 10 + lane] = u;
            }
        }
    }
    gsync();

    // ---------- P6: final agg (40 feats) + bias + log_softmax ----------
    {
        const __half2* gh = (const __half2*)d_g2;
        bool act = lane < 20;
        float2 al = act ? ((const float2*)d_al2)[lane] : make_float2(0.f, 0.f);
        float2 bb = act ? ((const float2*)b2)[lane] : make_float2(0.f, 0.f);
        for (int wid = bid * 8 + warp; wid < n; wid += NB * 8) {
            float di = d_dinv[wid];
            float2 A = make_float2(0.f, 0.f), B = A;
            if (act) {
                float2 f = __half22float2(gh[wid * 20 + lane]);
                A.x += di * f.x; A.y += di * f.y;
            }
            int k = d_off[wid], k1 = d_off[wid + 1];
            for (; k + 8 <= k1; k += 8) {
                int c[8]; float s[8]; float2 f[8];
#pragma unroll
                for (int j = 0; j < 8; j++) c[j] = d_col[k + j];
#pragma unroll
                for (int j = 0; j < 8; j++) s[j] = d_se[k + j];
                if (act) {
#pragma unroll
                    for (int j = 0; j < 8; j++) f[j] = __half22float2(gh[c[j] * 20 + lane]);
#pragma unroll
                    for (int j = 0; j < 8; j++) {
                        if (j & 1) { B.x += s[j] * f[j].x; B.y += s[j] * f[j].y; }
                        else       { A.x += s[j] * f[j].x; A.y += s[j] * f[j].y; }
                    }
                }
            }
            for (; k < k1; k++) {
                int c = d_col[k];
                float s = d_se[k];
                if (act) {
                    float2 f = __half22float2(gh[c * 20 + lane]);
                    B.x += s * f.x; B.y += s * f.y;
                }
            }
            float v0 = -1e30f, v1 = -1e30f;
            if (act) {
                v0 = (A.x + B.x) * al.x * di + bb.x;
                v1 = (A.y + B.y) * al.y * di + bb.y;
            }
            float m = fmaxf(v0, v1);
            for (int o = 16; o; o >>= 1) m = fmaxf(m, __shfl_xor_sync(FULLM, m, o));
            float se = act ? (expf(v0 - m) + expf(v1 - m)) : 0.f;
            for (int o = 16; o; o >>= 1) se += __shfl_xor_sync(FULLM, se, o);
            float lse = logf(se);
            if (act) {
                float2 r;
                r.x = v0 - m - lse;
                r.y = v1 - m - lse;
                ((float2*)out)[wid * 20 + lane] = r;
            }
        }
    }

    // ---------- P7: re-zero scratch for next graph replay (no barrier needed after) ----------
    for (int i = bid * TPB + tid; i < NMAX; i += NB * TPB) { d_cnt[i] = 0; d_cur[i] = 0; }
    if (bid == 0) d_musum[tid] = 0;
}

// ---------------- launch ----------------
extern "C" void kernel_launch(void* const* d_in, const int* in_sizes, int n_in,
                              void* d_out, int out_size) {
    const float* x  = (const float*)d_in[0];
    const void*  ei = d_in[1];

    int N = in_sizes[0] / 256;
    long long E = (long long)in_sizes[1] / 2;

    k_mega<<<NB, TPB>>>(x, ei, E, N,
                        (const float*)d_in[2], (const float*)d_in[3],
                        (const float*)d_in[4], (const float*)d_in[5],
                        (const float*)d_in[6], (const float*)d_in[7],
                        (float*)d_out);
}

// round 12
// speedup vs baseline: 1.0992x; 1.0992x over previous
#include <cuda_runtime.h>
#include <cuda_fp16.h>
#include <math.h>

#define FULLM 0xffffffffu
static const int NMAX = 100352;
static const int EMAX = 1700000;

// ---------------- device scratch ----------------
__device__ long long d_musum[256];
__device__ int      d_flag;
__device__ __align__(16) int d_cnt[NMAX];
__device__ int      d_cur[NMAX];
__device__ int      d_off[NMAX + 1];
__device__ float    d_dinv[NMAX];
__device__ __align__(16) int2 d_cs[EMAX];   // {src*32 (uint2-row index), dinv[src] bits}
__device__ uint2    d_ga[NMAX * 32];   // layer-0 cnt (fp16 exact)
__device__ uint2    d_gb[NMAX * 32];   // layer-1 cnt
__device__ uint2    d_g2[NMAX * 10];   // layer-2 cnt (40 feats)
__device__ __align__(16) unsigned d_wb0[8 * 128];
__device__ __align__(16) unsigned d_wb1[4 * 128];
__device__ __align__(16) unsigned d_wb2[4 * 40];
__device__ __align__(16) float d_al0[128];
__device__ __align__(16) float d_al1[128];
__device__ __align__(16) float d_al2[40];

__device__ __forceinline__ int detect64(const void* e) {
    const unsigned* w = (const unsigned*)e;
    int lane = threadIdx.x & 31;
    unsigned h0 = w[2 * lane + 1];
    unsigned h1 = w[64 + 2 * lane + 1];
    int z = __popc(__ballot_sync(FULLM, h0 == 0)) + __popc(__ballot_sync(FULLM, h1 == 0));
    return z >= 32;
}
__device__ __forceinline__ int ld_edge(const void* e, long long idx, int is64) {
    return is64 ? (int)((const long long*)e)[idx] : ((const int*)e)[idx];
}

// ============ L1: colsum partial (4-way MLP) | wprep | degree histogram ============
__global__ void k_prep(const float* __restrict__ x,
                       const float* __restrict__ W0,
                       const float* __restrict__ W1,
                       const float* __restrict__ W2,
                       const void* __restrict__ e, long long E, int n) {
    int bid = blockIdx.x;
    if (bid < 512) {
        int rows = (n + 511) / 512;
        int r0 = bid * rows, r1 = min(n, r0 + rows);
        int t = threadIdx.x;
        float s0 = 0.f, s1 = 0.f, s2 = 0.f, s3 = 0.f;
        int r = r0;
        for (; r + 4 <= r1; r += 4) {
            s0 += x[(long long)r * 256 + t];
            s1 += x[(long long)(r + 1) * 256 + t];
            s2 += x[(long long)(r + 2) * 256 + t];
            s3 += x[(long long)(r + 3) * 256 + t];
        }
        for (; r < r1; r++) s0 += x[(long long)r * 256 + t];
        float s = (s0 + s1) + (s2 + s3);
        long long q = llrintf(s * 4194304.f);
        atomicAdd((unsigned long long*)&d_musum[t], (unsigned long long)q);
    } else if (bid < 549) {
        int W = (bid - 512) * 8 + (threadIdx.x >> 5);
        int lane = threadIdx.x & 31;
        const float* Wsrc; unsigned* wbT; float* alpha; int K, OUT, j;
        if (W < 128)      { Wsrc = W0; wbT = d_wb0; alpha = d_al0; K = 256; OUT = 128; j = W; }
        else if (W < 256) { Wsrc = W1; wbT = d_wb1; alpha = d_al1; K = 128; OUT = 128; j = W - 128; }
        else if (W < 296) { Wsrc = W2; wbT = d_wb2; alpha = d_al2; K = 128; OUT = 40;  j = W - 256; }
        else return;
        float s = 0.f;
        int KW = K / 32;
        for (int w = 0; w < KW; w++) {
            float v = Wsrc[(long long)(w * 32 + lane) * OUT + j];
            s += fabsf(v);
            unsigned m = __ballot_sync(FULLM, v > 0.f);
            if (lane == 0) wbT[w * OUT + j] = m;
        }
        for (int o = 16; o; o >>= 1) s += __shfl_xor_sync(FULLM, s, o);
        if (lane == 0) alpha[j] = s / (float)K;
    } else {
        int is64 = detect64(e);
        long long i = (long long)(bid - 549) * blockDim.x + threadIdx.x;
        if (i < E) atomicAdd(&d_cnt[ld_edge(e, E + i, is64)], 1);
    }
}

// ============ L2: scan(block 0) | bnpack+bmm0 (1..wb64) | csr fill (spin) ============
__global__ void __launch_bounds__(256) k_pipe2(const float* __restrict__ x,
                                               const void* __restrict__ e,
                                               long long E, int n, int wb64) {
    int bid = blockIdx.x;
    if (bid == 0) {
        __shared__ int wsum[8];
        int t = threadIdx.x, lane = t & 31, wrp = t >> 5;
        int chunk = ((n + 255) / 256 + 3) & ~3;
        int c0 = t * chunk, c1 = min(n, c0 + chunk);
        int s = 0, i = c0;
        for (; i + 4 <= c1; i += 4) {
            int4 v = *(const int4*)(d_cnt + i);
            s += v.x + v.y + v.z + v.w;
        }
        for (; i < c1; i++) s += d_cnt[i];
        int incl = s;
        for (int o = 1; o < 32; o <<= 1) {
            int v = __shfl_up_sync(FULLM, incl, o);
            if (lane >= o) incl += v;
        }
        if (lane == 31) wsum[wrp] = incl;
        __syncthreads();
        if (wrp == 0) {
            int v = (lane < 8) ? wsum[lane] : 0;
            for (int o = 1; o < 8; o <<= 1) {
                int u = __shfl_up_sync(FULLM, v, o);
                if (lane >= o) v += u;
            }
            if (lane < 8) wsum[lane] = v;
        }
        __syncthreads();
        int run = incl - s + (wrp ? wsum[wrp - 1] : 0);
        for (i = c0; i < c1; i++) {
            int c = d_cnt[i];
            d_off[i] = run;
            run += c;
            d_dinv[i] = rsqrtf((float)(c + 1));
        }
        if (c0 < n && c1 == n) d_off[n] = run;
        __threadfence();
        __syncthreads();
        if (t == 0) atomicExch(&d_flag, 1);
    } else if (bid <= wb64) {
        __shared__ float smu[256];
        smu[threadIdx.x] = (float)((double)d_musum[threadIdx.x] / (4194304.0 * (double)n));
        __syncthreads();
        int warp = threadIdx.x >> 5, lane = threadIdx.x & 31;
        uint4 wv[8];
#pragma unroll
        for (int w = 0; w < 8; w++) wv[w] = *(const uint4*)&d_wb0[w * 128 + 4 * lane];
        int n0 = (bid - 1) * 64 + warp * 8;
#pragma unroll
        for (int i = 0; i < 8; i++) {
            int node = n0 + i;
            if (node >= n) break;
            const float* xr = x + (long long)node * 256;
            unsigned bw[8];
#pragma unroll
            for (int w = 0; w < 8; w++) {
                float v = xr[w * 32 + lane];
                bw[w] = __ballot_sync(FULLM, v > smu[w * 32 + lane]);
            }
            int p0 = 0, p1 = 0, p2 = 0, p3 = 0;
#pragma unroll
            for (int w = 0; w < 8; w++) {
                p0 += __popc(bw[w] ^ wv[w].x);
                p1 += __popc(bw[w] ^ wv[w].y);
                p2 += __popc(bw[w] ^ wv[w].z);
                p3 += __popc(bw[w] ^ wv[w].w);
            }
            __half2 h0 = __floats2half2_rn((float)(256 - 2 * p0), (float)(256 - 2 * p1));
            __half2 h1 = __floats2half2_rn((float)(256 - 2 * p2), (float)(256 - 2 * p3));
            uint2 u;
            u.x = *(unsigned*)&h0;
            u.y = *(unsigned*)&h1;
            d_ga[node * 32 + lane] = u;
        }
    } else {
        // CSR fill: prefetch edge, wait for scan flag, place interleaved record
        int is64 = detect64(e);
        long long i = (long long)(bid - wb64 - 1) * blockDim.x + threadIdx.x;
        int sv = 0, dv = 0;
        bool act = (i < E);
        if (act) {
            sv = ld_edge(e, i, is64);
            dv = ld_edge(e, E + i, is64);
        }
        if (threadIdx.x == 0) {
            while (atomicAdd(&d_flag, 0) == 0) __nanosleep(128);
            __threadfence();
        }
        __syncthreads();
        if (act) {
            int pos = d_off[dv] + atomicAdd(&d_cur[dv], 1);
            int2 cs;
            cs.x = sv * 32;                       // uint2-row base index
            cs.y = __float_as_int(d_dinv[sv]);
            d_cs[pos] = cs;
        }
    }
}

__device__ __forceinline__ void accH(float4& a, uint2 u, float s) {
    float2 f0 = __half22float2(*reinterpret_cast<__half2*>(&u.x));
    float2 f1 = __half22float2(*reinterpret_cast<__half2*>(&u.y));
    a.x += s * f0.x; a.y += s * f0.y; a.z += s * f1.x; a.w += s * f1.y;
}

// gather: one LDG.64 record per edge, pre-scaled row index
__device__ __forceinline__ float4 gather128(const uint2* __restrict__ gp, int wid, int lane) {
    float4 A = make_float4(0.f, 0.f, 0.f, 0.f), B = A;
    accH(A, gp[wid * 32 + lane], d_dinv[wid]);   // self loop
    int k = d_off[wid], k1 = d_off[wid + 1];
    for (; k + 8 <= k1; k += 8) {
        int2 cs[8]; uint2 u[8];
#pragma unroll
        for (int j = 0; j < 8; j++) cs[j] = d_cs[k + j];
#pragma unroll
        for (int j = 0; j < 8; j++) u[j] = gp[cs[j].x + lane];
#pragma unroll
        for (int j = 0; j < 8; j++) accH((j & 1) ? B : A, u[j], __int_as_float(cs[j].y));
    }
    if (k + 4 <= k1) {
        int2 cs[4]; uint2 u[4];
#pragma unroll
        for (int j = 0; j < 4; j++) cs[j] = d_cs[k + j];
#pragma unroll
        for (int j = 0; j < 4; j++) u[j] = gp[cs[j].x + lane];
#pragma unroll
        for (int j = 0; j < 4; j++) accH((j & 1) ? B : A, u[j], __int_as_float(cs[j].y));
        k += 4;
    }
    for (; k < k1; k++) {
        int2 cs = d_cs[k];
        accH(B, gp[cs.x + lane], __int_as_float(cs.y));
    }
    A.x += B.x; A.y += B.y; A.z += B.z; A.w += B.w;
    return A;
}

__device__ __forceinline__ void sign_words(float v0, float v1, float v2, float v3,
                                           int lane, unsigned bw[4]) {
    unsigned nib = (unsigned)(v0 > 0.f) | ((unsigned)(v1 > 0.f) << 1) |
                   ((unsigned)(v2 > 0.f) << 2) | ((unsigned)(v3 > 0.f) << 3);
    unsigned sh = nib << ((lane & 7) * 4);
    sh |= __shfl_xor_sync(FULLM, sh, 1);
    sh |= __shfl_xor_sync(FULLM, sh, 2);
    sh |= __shfl_xor_sync(FULLM, sh, 4);
#pragma unroll
    for (int wd = 0; wd < 4; wd++) bw[wd] = __shfl_sync(FULLM, sh, wd * 8);
}

// ============ L3: agg(layer-0) + sign + bmm1 -> d_gb ============
__global__ void k_agg1_bmm1(const float* __restrict__ bias, int n) {
    int wid = (blockIdx.x * blockDim.x + threadIdx.x) >> 5;
    int lane = threadIdx.x & 31;
    if (wid >= n) return;
    float4 A = gather128(d_ga, wid, lane);
    float di = d_dinv[wid];
    float4 al = ((const float4*)d_al0)[lane];
    float4 b  = ((const float4*)bias)[lane];
    float v0 = A.x * al.x * di + b.x;
    float v1 = A.y * al.y * di + b.y;
    float v2 = A.z * al.z * di + b.z;
    float v3 = A.w * al.w * di + b.w;
    unsigned bw[4];
    sign_words(v0, v1, v2, v3, lane, bw);
    uint4 wv[4];
#pragma unroll
    for (int w = 0; w < 4; w++) wv[w] = *(const uint4*)&d_wb1[w * 128 + 4 * lane];
    int p0 = 0, p1 = 0, p2 = 0, p3 = 0;
#pragma unroll
    for (int w = 0; w < 4; w++) {
        p0 += __popc(bw[w] ^ wv[w].x);
        p1 += __popc(bw[w] ^ wv[w].y);
        p2 += __popc(bw[w] ^ wv[w].z);
        p3 += __popc(bw[w] ^ wv[w].w);
    }
    __half2 h0 = __floats2half2_rn((float)(128 - 2 * p0), (float)(128 - 2 * p1));
    __half2 h1 = __floats2half2_rn((float)(128 - 2 * p2), (float)(128 - 2 * p3));
    uint2 u;
    u.x = *(unsigned*)&h0;
    u.y = *(unsigned*)&h1;
    d_gb[wid * 32 + lane] = u;
}

// ============ L4 (PROFILED): agg(layer-1) + sign + bmm2 -> d_g2 | re-zero ============
__global__ void k_agg2_bmm2(const float* __restrict__ bias, int n, int wpb) {
    if ((int)blockIdx.x >= wpb) {
        int b = blockIdx.x - wpb;
        for (int i = b * 256 + threadIdx.x; i < NMAX; i += 16 * 256) { d_cnt[i] = 0; d_cur[i] = 0; }
        if (b == 0) {
            if (threadIdx.x < 256) d_musum[threadIdx.x] = 0;
            if (threadIdx.x == 0) d_flag = 0;
        }
        return;
    }
    int wid = (blockIdx.x * blockDim.x + threadIdx.x) >> 5;
    int lane = threadIdx.x & 31;
    if (wid >= n) return;
    float4 A = gather128(d_gb, wid, lane);
    float di = d_dinv[wid];
    float4 al = ((const float4*)d_al1)[lane];
    float4 b  = ((const float4*)bias)[lane];
    float v0 = A.x * al.x * di + b.x;
    float v1 = A.y * al.y * di + b.y;
    float v2 = A.z * al.z * di + b.z;
    float v3 = A.w * al.w * di + b.w;
    unsigned bw[4];
    sign_words(v0, v1, v2, v3, lane, bw);
    if (lane < 10) {
        uint4 wv[4];
#pragma unroll
        for (int w = 0; w < 4; w++) wv[w] = *(const uint4*)&d_wb2[w * 40 + 4 * lane];
        int p0 = 0, p1 = 0, p2 = 0, p3 = 0;
#pragma unroll
        for (int w = 0; w < 4; w++) {
            p0 += __popc(bw[w] ^ wv[w].x);
            p1 += __popc(bw[w] ^ wv[w].y);
            p2 += __popc(bw[w] ^ wv[w].z);
            p3 += __popc(bw[w] ^ wv[w].w);
        }
        __half2 h0 = __floats2half2_rn((float)(128 - 2 * p0), (float)(128 - 2 * p1));
        __half2 h1 = __floats2half2_rn((float)(128 - 2 * p2), (float)(128 - 2 * p3));
        uint2 u;
        u.x = *(unsigned*)&h0;
        u.y = *(unsigned*)&h1;
        d_g2[wid * 10 + lane] = u;
    }
}

// ============ L5: final aggregation (40 feats) + bias + log_softmax ============
__global__ void k_agg_out(const float* __restrict__ bias, float* __restrict__ out, int n) {
    int wid = (blockIdx.x * blockDim.x + threadIdx.x) >> 5;
    int lane = threadIdx.x & 31;
    if (wid >= n) return;
    const __half2* gh = (const __half2*)d_g2;
    bool act = lane < 20;
    float di = d_dinv[wid];
    float2 A = make_float2(0.f, 0.f), B = A;
    if (act) {
        float2 f = __half22float2(gh[wid * 20 + lane]);
        A.x += di * f.x; A.y += di * f.y;
    }
    int k = d_off[wid], k1 = d_off[wid + 1];
    for (; k + 8 <= k1; k += 8) {
        int2 cs[8]; float2 f[8];
#pragma unroll
        for (int j = 0; j < 8; j++) cs[j] = d_cs[k + j];
        if (act) {
#pragma unroll
            for (int j = 0; j < 8; j++) {
                int row20 = (cs[j].x * 5) >> 3;        // c*32 -> c*20
                f[j] = __half22float2(gh[row20 + lane]);
            }
#pragma unroll
            for (int j = 0; j < 8; j++) {
                float s = __int_as_float(cs[j].y);
                if (j & 1) { B.x += s * f[j].x; B.y += s * f[j].y; }
                else       { A.x += s * f[j].x; A.y += s * f[j].y; }
            }
        }
    }
    for (; k < k1; k++) {
        int2 cs = d_cs[k];
        if (act) {
            int row20 = (cs.x * 5) >> 3;
            float2 f = __half22float2(gh[row20 + lane]);
            float s = __int_as_float(cs.y);
            B.x += s * f.x; B.y += s * f.y;
        }
    }
    float v0 = -1e30f, v1 = -1e30f;
    if (act) {
        float2 al = ((const float2*)d_al2)[lane];
        float2 b  = ((const float2*)bias)[lane];
        v0 = (A.x + B.x) * al.x * di + b.x;
        v1 = (A.y + B.y) * al.y * di + b.y;
    }
    float m = fmaxf(v0, v1);
    for (int o = 16; o; o >>= 1) m = fmaxf(m, __shfl_xor_sync(FULLM, m, o));
    float se = act ? (expf(v0 - m) + expf(v1 - m)) : 0.f;
    for (int o = 16; o; o >>= 1) se += __shfl_xor_sync(FULLM, se, o);
    float lse = logf(se);
    if (act) {
        float2 r;
        r.x = v0 - m - lse;
        r.y = v1 - m - lse;
        ((float2*)out)[wid * 20 + lane] = r;
    }
}

// ---------------- launch ----------------
extern "C" void kernel_launch(void* const* d_in, const int* in_sizes, int n_in,
                              void* d_out, int out_size) {
    const float* x  = (const float*)d_in[0];
    const void*  ei = d_in[1];
    const float* b0 = (const float*)d_in[3];
    const float* b1 = (const float*)d_in[5];
    const float* b2 = (const float*)d_in[7];
    float* out = (float*)d_out;

    int N = in_sizes[0] / 256;
    long long E = (long long)in_sizes[1] / 2;

    int eb   = (int)((E + 255) / 256);
    int wb64 = (N + 63) / 64;
    int wpb  = (N + 7) / 8;

    k_prep<<<549 + eb, 256>>>(x, (const float*)d_in[2], (const float*)d_in[4],
                              (const float*)d_in[6], ei, E, N);   // 1
    k_pipe2<<<1 + wb64 + eb, 256>>>(x, ei, E, N, wb64);           // 2: scan|bnpack+bmm0|csr
    k_agg1_bmm1<<<wpb, 256>>>(b0, N);                             // 3
    k_agg2_bmm2<<<wpb + 16, 256>>>(b1, N, wpb);                   // 4 (PROFILED)
    k_agg_out<<<wpb, 256>>>(b2, out, N);                          // 5
}